// round 17
// baseline (speedup 1.0000x reference)
#include <cuda_runtime.h>
#include <cstdint>

// ---------------- problem constants ----------------
#define BB 2
#define TT 1024
#define EE 1024
#define HH 16
#define DD 64
#define LL 6
#define FF 4096
#define VV 32000
#define RR (BB*TT)   // 2048 token rows

// ---------------- device scratch (static, no allocations) ----------------
__device__ float g_x [RR*EE];
__device__ float g_h [RR*EE];
__device__ float g_q [RR*EE];
__device__ float g_k [RR*EE];
__device__ float g_v [RR*EE];
__device__ float g_o [RR*EE];
__device__ float g_ff[RR*FF];

__device__ __forceinline__ uint32_t smem_u32(const void* p) {
    uint32_t a;
    asm("{ .reg .u64 t; cvta.to.shared.u64 t, %1; cvt.u32.u64 %0, t; }"
        : "=r"(a) : "l"(p));
    return a;
}

__device__ __forceinline__ void ldsm_x4(uint32_t& r0, uint32_t& r1,
                                        uint32_t& r2, uint32_t& r3, uint32_t addr) {
    asm volatile("ldmatrix.sync.aligned.m8n8.x4.shared.b16 {%0,%1,%2,%3}, [%4];"
                 : "=r"(r0), "=r"(r1), "=r"(r2), "=r"(r3) : "r"(addr));
}

__device__ __forceinline__ void mma_bf16(float& c0, float& c1, float& c2, float& c3,
                                         uint32_t a0, uint32_t a1, uint32_t a2, uint32_t a3,
                                         uint32_t b0, uint32_t b1) {
    asm volatile("mma.sync.aligned.m16n8k16.row.col.f32.bf16.bf16.f32 "
                 "{%0,%1,%2,%3}, {%4,%5,%6,%7}, {%8,%9}, {%0,%1,%2,%3};"
                 : "+f"(c0), "+f"(c1), "+f"(c2), "+f"(c3)
                 : "r"(a0), "r"(a1), "r"(a2), "r"(a3), "r"(b0), "r"(b1));
}

// split two fp32 (k-consecutive x0,x1) into packed bf16x2 hi and lo
__device__ __forceinline__ void split2(float x0, float x1, uint32_t& h, uint32_t& l) {
    uint32_t hh;
    asm("cvt.rn.bf16x2.f32 %0, %1, %2;" : "=r"(hh) : "f"(x1), "f"(x0));
    float h0 = __uint_as_float(hh << 16);
    float h1 = __uint_as_float(hh & 0xFFFF0000u);
    float l0 = x0 - h0, l1 = x1 - h1;
    uint32_t ll;
    asm("cvt.rn.bf16x2.f32 %0, %1, %2;" : "=r"(ll) : "f"(l1), "f"(l0));
    h = hh; l = ll;
}

// 3 mma terms: ah*bh + ah*bl + al*bh
#define MMA3(ACC, AH, AL, BH0, BH1, BL0, BL1) do { \
    mma_bf16((ACC)[0], (ACC)[1], (ACC)[2], (ACC)[3], \
             (AH)[0], (AH)[1], (AH)[2], (AH)[3], (BH0), (BH1)); \
    mma_bf16((ACC)[0], (ACC)[1], (ACC)[2], (ACC)[3], \
             (AH)[0], (AH)[1], (AH)[2], (AH)[3], (BL0), (BL1)); \
    mma_bf16((ACC)[0], (ACC)[1], (ACC)[2], (ACC)[3], \
             (AL)[0], (AL)[1], (AL)[2], (AL)[3], (BH0), (BH1)); \
} while (0)

// ================= 3xBF16 tensor-core GEMM (R13 version — best measured) ======
#define TG_SMEM 49152

template<bool BIAS, bool RELU, bool RESID>
__global__ void __launch_bounds__(128, 2)
k_tgemm(const float* __restrict__ A, const float* __restrict__ B,
        const float* __restrict__ bias, const float* __restrict__ resid,
        float* __restrict__ C, int M, int N, int K) {
    extern __shared__ char smem[];
    const uint32_t sb = smem_u32(smem);
    const int tid = threadIdx.x, lane = tid & 31, wid = tid >> 5;
    const int wm = wid & 1, wn = wid >> 1;           // 2 x 2 warp grid
    const int rowBase = blockIdx.x * 128;
    const int colBase = blockIdx.y * 64;

    float acc[4][4][4];
    #pragma unroll
    for (int i = 0; i < 4; i++)
        #pragma unroll
        for (int j = 0; j < 4; j++)
            #pragma unroll
            for (int r = 0; r < 4; r++) acc[i][j][r] = 0.f;

    const int a_m = tid >> 3, a_kq = tid & 7;
    const int b_n = tid & 63, b_q0 = tid >> 6;
    const int b_s = (b_n >> 3) & 7;

    const int a_m_in = (lane & 7) + ((lane >> 3) & 1) * 8;
    const int a_kb   = ((lane >> 4) & 1) * 16;
    const int b_n_in = (lane & 7) + ((lane >> 4) & 1) * 8;
    const int b_kb   = ((lane >> 3) & 1) * 16;

    const int nchunk = K >> 5;
    float4 pa[8], pb[4];

    {
        #pragma unroll
        for (int i = 0; i < 8; i++) {
            int m = a_m + 16 * i;
            pa[i] = *(const float4*)(A + (size_t)(rowBase + m) * K + a_kq * 4);
        }
        #pragma unroll
        for (int i = 0; i < 4; i++) {
            int kq = (b_q0 + 2 * i) ^ b_s;
            const float* bp = B + (size_t)(kq * 4) * N + colBase + b_n;
            pb[i] = make_float4(bp[0], bp[(size_t)N], bp[(size_t)2 * N], bp[(size_t)3 * N]);
        }
        #pragma unroll
        for (int i = 0; i < 8; i++) {
            int m = a_m + 16 * i;
            uint32_t h01, l01, h23, l23;
            split2(pa[i].x, pa[i].y, h01, l01);
            split2(pa[i].z, pa[i].w, h23, l23);
            uint32_t off = (uint32_t)(m * 64 + ((a_kq * 8) ^ (((m >> 1) & 3) << 4)));
            *(uint2*)(smem + off)        = make_uint2(h01, h23);
            *(uint2*)(smem + 8192 + off) = make_uint2(l01, l23);
        }
        #pragma unroll
        for (int i = 0; i < 4; i++) {
            int kq = (b_q0 + 2 * i) ^ b_s;
            uint32_t h01, l01, h23, l23;
            split2(pb[i].x, pb[i].y, h01, l01);
            split2(pb[i].z, pb[i].w, h23, l23);
            uint32_t off = (uint32_t)(b_n * 64 + ((kq * 8) ^ (((b_n >> 1) & 3) << 4)));
            *(uint2*)(smem + 16384 + off) = make_uint2(h01, h23);
            *(uint2*)(smem + 20480 + off) = make_uint2(l01, l23);
        }
    }
    __syncthreads();

    for (int c = 0; c < nchunk; c++) {
        const uint32_t base = sb + (uint32_t)(c & 1) * 24576;
        const uint32_t ah = base, al = base + 8192;
        const uint32_t bh = base + 16384, bl = base + 20480;

        if (c + 1 < nchunk) {
            int k0 = (c + 1) << 5;
            #pragma unroll
            for (int i = 0; i < 8; i++) {
                int m = a_m + 16 * i;
                pa[i] = *(const float4*)(A + (size_t)(rowBase + m) * K + k0 + a_kq * 4);
            }
            #pragma unroll
            for (int i = 0; i < 4; i++) {
                int kq = (b_q0 + 2 * i) ^ b_s;
                const float* bp = B + (size_t)(k0 + kq * 4) * N + colBase + b_n;
                pb[i] = make_float4(bp[0], bp[(size_t)N], bp[(size_t)2 * N], bp[(size_t)3 * N]);
            }
        }

        #pragma unroll
        for (int kt = 0; kt < 2; kt++) {
            uint32_t afh[4][4], afl[4][4], bfh[2][4], bfl[2][4];
            #pragma unroll
            for (int mt = 0; mt < 4; mt++) {
                int row = wm * 64 + mt * 16 + a_m_in;
                uint32_t off = (uint32_t)(row * 64 + ((kt * 32 + a_kb) ^ (((row >> 1) & 3) << 4)));
                ldsm_x4(afh[mt][0], afh[mt][1], afh[mt][2], afh[mt][3], ah + off);
                ldsm_x4(afl[mt][0], afl[mt][1], afl[mt][2], afl[mt][3], al + off);
            }
            #pragma unroll
            for (int ntp = 0; ntp < 2; ntp++) {
                int row = wn * 32 + ntp * 16 + b_n_in;
                uint32_t off = (uint32_t)(row * 64 + ((kt * 32 + b_kb) ^ (((row >> 1) & 3) << 4)));
                ldsm_x4(bfh[ntp][0], bfh[ntp][1], bfh[ntp][2], bfh[ntp][3], bh + off);
                ldsm_x4(bfl[ntp][0], bfl[ntp][1], bfl[ntp][2], bfl[ntp][3], bl + off);
            }
            #pragma unroll
            for (int mt = 0; mt < 4; mt++)
                #pragma unroll
                for (int nt = 0; nt < 4; nt++) {
                    const int np = nt >> 1, ne = (nt & 1) * 2;
                    MMA3(acc[mt][nt], afh[mt], afl[mt],
                         bfh[np][ne], bfh[np][ne + 1], bfl[np][ne], bfl[np][ne + 1]);
                }
        }

        if (c + 1 < nchunk) {
            char* nb = smem + ((c + 1) & 1) * 24576;
            #pragma unroll
            for (int i = 0; i < 8; i++) {
                int m = a_m + 16 * i;
                uint32_t h01, l01, h23, l23;
                split2(pa[i].x, pa[i].y, h01, l01);
                split2(pa[i].z, pa[i].w, h23, l23);
                uint32_t off = (uint32_t)(m * 64 + ((a_kq * 8) ^ (((m >> 1) & 3) << 4)));
                *(uint2*)(nb + off)        = make_uint2(h01, h23);
                *(uint2*)(nb + 8192 + off) = make_uint2(l01, l23);
            }
            #pragma unroll
            for (int i = 0; i < 4; i++) {
                int kq = (b_q0 + 2 * i) ^ b_s;
                uint32_t h01, l01, h23, l23;
                split2(pb[i].x, pb[i].y, h01, l01);
                split2(pb[i].z, pb[i].w, h23, l23);
                uint32_t off = (uint32_t)(b_n * 64 + ((kq * 8) ^ (((b_n >> 1) & 3) << 4)));
                *(uint2*)(nb + 16384 + off) = make_uint2(h01, h23);
                *(uint2*)(nb + 20480 + off) = make_uint2(l01, l23);
            }
            __syncthreads();
        }
    }

    const int row0 = lane >> 2, col0 = (lane & 3) * 2;
    #pragma unroll
    for (int mt = 0; mt < 4; mt++) {
        #pragma unroll
        for (int nt = 0; nt < 4; nt++) {
            int gm = rowBase + wm * 64 + mt * 16 + row0;
            int gn = colBase + wn * 32 + nt * 8 + col0;
            float o0 = acc[mt][nt][0], o1 = acc[mt][nt][1];
            float o2 = acc[mt][nt][2], o3 = acc[mt][nt][3];
            if (BIAS) {
                float bv0 = bias[gn], bv1 = bias[gn + 1];
                o0 += bv0; o1 += bv1; o2 += bv0; o3 += bv1;
            }
            size_t p0 = (size_t)gm * N + gn;
            size_t p1 = (size_t)(gm + 8) * N + gn;
            if (RESID) {
                float2 r0v = *(const float2*)(resid + p0);
                float2 r1v = *(const float2*)(resid + p1);
                o0 += r0v.x; o1 += r0v.y; o2 += r1v.x; o3 += r1v.y;
            }
            if (RELU) {
                o0 = fmaxf(o0, 0.f); o1 = fmaxf(o1, 0.f);
                o2 = fmaxf(o2, 0.f); o3 = fmaxf(o3, 0.f);
            }
            *(float2*)(C + p0) = make_float2(o0, o1);
            *(float2*)(C + p1) = make_float2(o2, o3);
        }
    }
}

// ================= fused flash attention =================
// One CTA per (bh, 128-row q-tile). 256 threads, 8 warps; warp owns 16 q-rows.
// Streams 128-wide K/V tiles through SMEM; S lives in registers; online softmax.
// SMEM: Qh@0 Ql@16K (128x64 bf16, 128B rows, scores swizzle)
//       Kh@32K Kl@48K (same layout)
//       Vh@64K Vl@80K (4 sub-tiles of [64 d][32 tok], 64B rows, k_av swizzle)
#define FLASH_SMEM 98304

__global__ void __launch_bounds__(256, 1)
k_flash(const float* __restrict__ q, const float* __restrict__ k,
        const float* __restrict__ v, float* __restrict__ o) {
    extern __shared__ char smem[];
    const uint32_t sb = smem_u32(smem);
    const int bh = blockIdx.y, b = bh >> 4, h = bh & 15;
    const int qt = gridDim.x - 1 - blockIdx.x;   // longest CTAs launch first
    const int q0 = qt * 128;                     // q0 in [0, TT)
    const int nkt = qt + 1;
    const int tid = threadIdx.x, lane = tid & 31, wid = tid >> 5;

    const int a_m_in = (lane & 7) + ((lane >> 3) & 1) * 8;
    const int a_kb   = ((lane >> 4) & 1) * 16;
    const int b_n_in = (lane & 7) + ((lane >> 4) & 1) * 8;
    const int b_kb   = ((lane >> 3) & 1) * 16;

    const int vb_n = tid & 63, vb_q0 = tid >> 6;      // V loads (k_av pattern)
    const int vb_s = (vb_n >> 3) & 7;

    // ---- load Q tile once (hi/lo, scores layout) ----
    #pragma unroll
    for (int i = 0; i < 8; i++) {
        int idx = tid + 256 * i;
        int row = idx >> 4, dq = idx & 15;
        float4 vq = *(const float4*)(q + (size_t)(b * TT + q0 + row) * EE + h * DD + dq * 4);
        uint32_t h01, l01, h23, l23;
        split2(vq.x, vq.y, h01, l01);
        split2(vq.z, vq.w, h23, l23);
        uint32_t off = (uint32_t)(row * 128 + ((dq * 8) ^ ((row & 7) << 4)));
        *(uint2*)(smem + off)         = make_uint2(h01, h23);
        *(uint2*)(smem + 16384 + off) = make_uint2(l01, l23);
    }

    float Oacc[8][4];
    #pragma unroll
    for (int i = 0; i < 8; i++)
        #pragma unroll
        for (int r = 0; r < 4; r++) Oacc[i][r] = 0.f;
    float m0 = -1e30f, m1 = -1e30f, s0 = 0.f, s1 = 0.f;

    const int qrow0 = q0 + wid * 16 + (lane >> 2);   // rows owned: qrow0, qrow0+8

    for (int kt = 0; kt < nkt; kt++) {
        const int k0 = kt * 128;
        if (kt > 0) __syncthreads();   // all warps done reading previous K/V
        // ---- load K tile (scores layout) ----
        #pragma unroll
        for (int i = 0; i < 8; i++) {
            int idx = tid + 256 * i;
            int row = idx >> 4, dq = idx & 15;
            float4 vk = *(const float4*)(k + (size_t)(b * TT + k0 + row) * EE + h * DD + dq * 4);
            uint32_t h01, l01, h23, l23;
            split2(vk.x, vk.y, h01, l01);
            split2(vk.z, vk.w, h23, l23);
            uint32_t off = (uint32_t)(row * 128 + ((dq * 8) ^ ((row & 7) << 4)));
            *(uint2*)(smem + 32768 + off) = make_uint2(h01, h23);
            *(uint2*)(smem + 49152 + off) = make_uint2(l01, l23);
        }
        // ---- load V tile (4 sub-tiles, k_av layout: rows = d, cols = token) ----
        #pragma unroll
        for (int sj = 0; sj < 4; sj++) {
            #pragma unroll
            for (int i = 0; i < 2; i++) {
                int kq = (vb_q0 + 4 * i) ^ vb_s;
                const float* bp = v + (size_t)(b * TT + k0 + sj * 32 + kq * 4) * EE + h * DD + vb_n;
                float4 pv = make_float4(bp[0], bp[(size_t)EE], bp[(size_t)2 * EE], bp[(size_t)3 * EE]);
                uint32_t h01, l01, h23, l23;
                split2(pv.x, pv.y, h01, l01);
                split2(pv.z, pv.w, h23, l23);
                uint32_t off = (uint32_t)(sj * 4096 + vb_n * 64 + ((kq * 8) ^ (((vb_n >> 1) & 3) << 4)));
                *(uint2*)(smem + 65536 + off) = make_uint2(h01, h23);
                *(uint2*)(smem + 81920 + off) = make_uint2(l01, l23);
            }
        }
        __syncthreads();

        // ---- S = Q K^T for this warp's 16 rows x 128 cols ----
        float S[16][4];
        #pragma unroll
        for (int nt = 0; nt < 16; nt++)
            #pragma unroll
            for (int r = 0; r < 4; r++) S[nt][r] = 0.f;
        #pragma unroll
        for (int dt = 0; dt < 4; dt++) {
            uint32_t qh[4], ql[4];
            int row = wid * 16 + a_m_in;
            uint32_t offq = (uint32_t)(row * 128 + ((dt * 32 + a_kb) ^ ((row & 7) << 4)));
            ldsm_x4(qh[0], qh[1], qh[2], qh[3], sb + offq);
            ldsm_x4(ql[0], ql[1], ql[2], ql[3], sb + 16384 + offq);
            #pragma unroll
            for (int ntp = 0; ntp < 8; ntp++) {
                uint32_t kh[4], kl[4];
                int krow = ntp * 16 + b_n_in;
                uint32_t offk = (uint32_t)(krow * 128 + ((dt * 32 + b_kb) ^ ((krow & 7) << 4)));
                ldsm_x4(kh[0], kh[1], kh[2], kh[3], sb + 32768 + offk);
                ldsm_x4(kl[0], kl[1], kl[2], kl[3], sb + 49152 + offk);
                MMA3(S[ntp * 2],     qh, ql, kh[0], kh[1], kl[0], kl[1]);
                MMA3(S[ntp * 2 + 1], qh, ql, kh[2], kh[3], kl[2], kl[3]);
            }
        }

        // ---- scale + causal mask (only diagonal tile can be partial) ----
        const bool diag = (kt == nkt - 1);
        #pragma unroll
        for (int nt = 0; nt < 16; nt++) {
            int cb = k0 + nt * 8 + 2 * (lane & 3);
            S[nt][0] = (!diag || cb     <= qrow0)     ? S[nt][0] * 0.125f : -1e30f;
            S[nt][1] = (!diag || cb + 1 <= qrow0)     ? S[nt][1] * 0.125f : -1e30f;
            S[nt][2] = (!diag || cb     <= qrow0 + 8) ? S[nt][2] * 0.125f : -1e30f;
            S[nt][3] = (!diag || cb + 1 <= qrow0 + 8) ? S[nt][3] * 0.125f : -1e30f;
        }

        // ---- row max (4 lanes per row: shfl_xor 1,2) ----
        float tm0 = -1e30f, tm1 = -1e30f;
        #pragma unroll
        for (int nt = 0; nt < 16; nt++) {
            tm0 = fmaxf(tm0, fmaxf(S[nt][0], S[nt][1]));
            tm1 = fmaxf(tm1, fmaxf(S[nt][2], S[nt][3]));
        }
        tm0 = fmaxf(tm0, __shfl_xor_sync(0xffffffffu, tm0, 1));
        tm0 = fmaxf(tm0, __shfl_xor_sync(0xffffffffu, tm0, 2));
        tm1 = fmaxf(tm1, __shfl_xor_sync(0xffffffffu, tm1, 1));
        tm1 = fmaxf(tm1, __shfl_xor_sync(0xffffffffu, tm1, 2));

        float mn0 = fmaxf(m0, tm0), mn1 = fmaxf(m1, tm1);
        float f0 = __expf(m0 - mn0), f1 = __expf(m1 - mn1);
        s0 *= f0; s1 *= f1;
        #pragma unroll
        for (int i = 0; i < 8; i++) {
            Oacc[i][0] *= f0; Oacc[i][1] *= f0;
            Oacc[i][2] *= f1; Oacc[i][3] *= f1;
        }
        m0 = mn0; m1 = mn1;

        // ---- P = exp(S - m), accumulate row sums ----
        float ps0 = 0.f, ps1 = 0.f;
        #pragma unroll
        for (int nt = 0; nt < 16; nt++) {
            S[nt][0] = __expf(S[nt][0] - m0);
            S[nt][1] = __expf(S[nt][1] - m0);
            S[nt][2] = __expf(S[nt][2] - m1);
            S[nt][3] = __expf(S[nt][3] - m1);
            ps0 += S[nt][0] + S[nt][1];
            ps1 += S[nt][2] + S[nt][3];
        }
        ps0 += __shfl_xor_sync(0xffffffffu, ps0, 1);
        ps0 += __shfl_xor_sync(0xffffffffu, ps0, 2);
        ps1 += __shfl_xor_sync(0xffffffffu, ps1, 1);
        ps1 += __shfl_xor_sync(0xffffffffu, ps1, 2);
        s0 += ps0; s1 += ps1;

        // ---- O += P @ V : 8 k16-chunks, P frags direct from S regs ----
        #pragma unroll
        for (int j = 0; j < 8; j++) {
            uint32_t ph[4], pl[4];
            split2(S[2*j][0],     S[2*j][1],     ph[0], pl[0]);
            split2(S[2*j][2],     S[2*j][3],     ph[1], pl[1]);
            split2(S[2*j + 1][0], S[2*j + 1][1], ph[2], pl[2]);
            split2(S[2*j + 1][2], S[2*j + 1][3], ph[3], pl[3]);
            const int sj = j >> 1, ktv = j & 1;
            #pragma unroll
            for (int ntp = 0; ntp < 4; ntp++) {
                uint32_t vfh[4], vfl[4];
                int vrow = ntp * 16 + b_n_in;
                uint32_t offv = (uint32_t)(sj * 4096 + vrow * 64 +
                                ((ktv * 32 + b_kb) ^ (((vrow >> 1) & 3) << 4)));
                ldsm_x4(vfh[0], vfh[1], vfh[2], vfh[3], sb + 65536 + offv);
                ldsm_x4(vfl[0], vfl[1], vfl[2], vfl[3], sb + 81920 + offv);
                MMA3(Oacc[ntp * 2],     ph, pl, vfh[0], vfh[1], vfl[0], vfl[1]);
                MMA3(Oacc[ntp * 2 + 1], ph, pl, vfh[2], vfh[3], vfl[2], vfl[3]);
            }
        }
    }

    // ---- normalize and write O ----
    float inv0 = 1.f / s0, inv1 = 1.f / s1;
    const int col0 = 2 * (lane & 3);
    #pragma unroll
    for (int dt = 0; dt < 8; dt++) {
        int gn = h * DD + dt * 8 + col0;
        size_t p0 = (size_t)(b * TT + qrow0) * EE + gn;
        size_t p1 = (size_t)(b * TT + qrow0 + 8) * EE + gn;
        *(float2*)(o + p0) = make_float2(Oacc[dt][0] * inv0, Oacc[dt][1] * inv0);
        *(float2*)(o + p1) = make_float2(Oacc[dt][2] * inv1, Oacc[dt][3] * inv1);
    }
}

// ---------------- embed ----------------
__global__ void k_embed(const int* __restrict__ idx, const float* __restrict__ tok,
                        const float* __restrict__ pos, float* __restrict__ x) {
    int r = blockIdx.x;
    int t = r & (TT - 1);
    int tokid = idx[r];
    const float4* te = (const float4*)(tok + (size_t)tokid * EE);
    const float4* pe = (const float4*)(pos + (size_t)t * EE);
    float4* xr = (float4*)(x + (size_t)r * EE);
    int c = threadIdx.x;
    float4 a = te[c], b = pe[c];
    xr[c] = make_float4(a.x + b.x, a.y + b.y, a.z + b.z, a.w + b.w);
}

// ---------------- block reduce ----------------
__device__ __forceinline__ float blockReduceSum(float val, float* red) {
    int tid = threadIdx.x;
    #pragma unroll
    for (int o = 16; o; o >>= 1) val += __shfl_xor_sync(0xffffffffu, val, o);
    if ((tid & 31) == 0) red[tid >> 5] = val;
    __syncthreads();
    if (tid < 32) {
        float v = (tid < 8) ? red[tid] : 0.f;
        #pragma unroll
        for (int o = 4; o; o >>= 1) v += __shfl_xor_sync(0xffffffffu, v, o);
        if (tid == 0) red[0] = v;
    }
    __syncthreads();
    float r = red[0];
    __syncthreads();
    return r;
}

// ---------------- layernorm ----------------
__global__ void k_ln(const float* __restrict__ x, const float* __restrict__ g,
                     const float* __restrict__ b, float* __restrict__ out) {
    __shared__ float red[32];
    int row = blockIdx.x, tid = threadIdx.x;
    const float* xr = x + (size_t)row * EE;
    float v[4];
    float s = 0.f;
    #pragma unroll
    for (int i = 0; i < 4; i++) { v[i] = xr[tid + 256 * i]; s += v[i]; }
    s = blockReduceSum(s, red);
    float mean = s * (1.f / EE);
    float s2 = 0.f;
    #pragma unroll
    for (int i = 0; i < 4; i++) { float d = v[i] - mean; s2 += d * d; }
    s2 = blockReduceSum(s2, red);
    float inv = rsqrtf(s2 * (1.f / EE) + 1e-5f);
    #pragma unroll
    for (int i = 0; i < 4; i++) {
        int c = tid + 256 * i;
        out[(size_t)row * EE + c] = (v[i] - mean) * inv * g[c] + b[c];
    }
}

// ---------------- host orchestration ----------------
extern "C" void kernel_launch(void* const* d_in, const int* in_sizes, int n_in,
                              void* d_out, int out_size) {
    const int*   idx  = (const int*)  d_in[0];
    const float* tok  = (const float*)d_in[1];
    const float* pos  = (const float*)d_in[2];
    const float* Wq   = (const float*)d_in[3];
    const float* Wk   = (const float*)d_in[4];
    const float* Wv   = (const float*)d_in[5];
    const float* Wp   = (const float*)d_in[6];
    const float* bp   = (const float*)d_in[7];
    const float* g1   = (const float*)d_in[8];
    const float* b1   = (const float*)d_in[9];
    const float* g2   = (const float*)d_in[10];
    const float* b2   = (const float*)d_in[11];
    const float* W1   = (const float*)d_in[12];
    const float* bf1  = (const float*)d_in[13];
    const float* W2   = (const float*)d_in[14];
    const float* bf2  = (const float*)d_in[15];
    const float* gf   = (const float*)d_in[16];
    const float* bff  = (const float*)d_in[17];
    const float* Wlm  = (const float*)d_in[18];
    const float* blm  = (const float*)d_in[19];
    float* out = (float*)d_out;

    float *x, *h, *q, *k, *v, *o, *ff;
    cudaGetSymbolAddress((void**)&x,  g_x);
    cudaGetSymbolAddress((void**)&h,  g_h);
    cudaGetSymbolAddress((void**)&q,  g_q);
    cudaGetSymbolAddress((void**)&k,  g_k);
    cudaGetSymbolAddress((void**)&v,  g_v);
    cudaGetSymbolAddress((void**)&o,  g_o);
    cudaGetSymbolAddress((void**)&ff, g_ff);

    cudaFuncSetAttribute(k_tgemm<false,false,false>,
                         cudaFuncAttributeMaxDynamicSharedMemorySize, TG_SMEM);
    cudaFuncSetAttribute(k_tgemm<true,false,true>,
                         cudaFuncAttributeMaxDynamicSharedMemorySize, TG_SMEM);
    cudaFuncSetAttribute(k_tgemm<true,true,false>,
                         cudaFuncAttributeMaxDynamicSharedMemorySize, TG_SMEM);
    cudaFuncSetAttribute(k_tgemm<true,false,false>,
                         cudaFuncAttributeMaxDynamicSharedMemorySize, TG_SMEM);
    cudaFuncSetAttribute(k_flash,
                         cudaFuncAttributeMaxDynamicSharedMemorySize, FLASH_SMEM);

    k_embed<<<RR, 256>>>(idx, tok, pos, x);

    // grid: x = M/128 (row tiles), y = N/64 (col tiles)
    dim3 gEE(RR / 128, EE / 64);       // (16, 16)
    dim3 gFF(RR / 128, FF / 64);       // (16, 64)
    dim3 gLM(RR / 128, VV / 64);       // (16, 500)

    for (int l = 0; l < LL; l++) {
        const float* wq = Wq + (size_t)l * EE * EE;
        const float* wk = Wk + (size_t)l * EE * EE;
        const float* wv = Wv + (size_t)l * EE * EE;
        const float* wp = Wp + (size_t)l * EE * EE;
        const float* w1 = W1 + (size_t)l * EE * FF;
        const float* w2 = W2 + (size_t)l * FF * EE;

        k_ln<<<RR, 256>>>(x, g1 + l * EE, b1 + l * EE, h);
        k_tgemm<false,false,false><<<gEE, 128, TG_SMEM>>>(h, wq, nullptr, nullptr, q, RR, EE, EE);
        k_tgemm<false,false,false><<<gEE, 128, TG_SMEM>>>(h, wk, nullptr, nullptr, k, RR, EE, EE);
        k_tgemm<false,false,false><<<gEE, 128, TG_SMEM>>>(h, wv, nullptr, nullptr, v, RR, EE, EE);

        // TT/128 = 8 q-tiles per (b,h) — NOT RR/128
        k_flash<<<dim3(TT / 128, BB * HH), 256, FLASH_SMEM>>>(q, k, v, o);

        // x = x + o @ Wp + bp
        k_tgemm<true,false,true><<<gEE, 128, TG_SMEM>>>(o, wp, bp + l * EE, x, x, RR, EE, EE);

        k_ln<<<RR, 256>>>(x, g2 + l * EE, b2 + l * EE, h);
        // ff = relu(h @ W1 + bf1)
        k_tgemm<true,true,false><<<gFF, 128, TG_SMEM>>>(h, w1, bf1 + l * FF, nullptr, ff, RR, FF, EE);
        // x = x + ff @ W2 + bf2
        k_tgemm<true,false,true><<<gEE, 128, TG_SMEM>>>(ff, w2, bf2 + l * EE, x, x, RR, EE, FF);
    }

    k_ln<<<RR, 256>>>(x, gf, bff, h);
    k_tgemm<true,false,false><<<gLM, 128, TG_SMEM>>>(h, Wlm, blm, nullptr, out, RR, VV, EE);
}